// round 15
// baseline (speedup 1.0000x reference)
#include <cuda_runtime.h>
#include <cuda_fp16.h>
#include <stdint.h>

#define NF     64
#define C      128
#define EF     32
#define MAXN   100000
#define MAXE   1600000
#define BN_EPS 1e-5f
#define TILE_E 32
#define STAGES 4

// ---------------- scratch (device globals; no allocations) ----------------
__device__ __align__(16) __half g_hsrc[(size_t)MAXN * C];   // 25.6 MB (fp16)
__device__ __align__(16) __half g_hdst[(size_t)MAXN * C];   // 25.6 MB (fp16)
__device__ __align__(16) __half g_mh[(size_t)MAXE * C];     // 409.6 MB (fp16 m)
__device__ __align__(16) float  g_h[(size_t)MAXN * NF];     // 25.6 MB
__device__ __align__(16) float  g_sum[C];
__device__ __align__(16) float  g_sumsq[C];
__device__ __align__(16) float  g_bn_s[C];
__device__ __align__(16) float  g_bn_b[C];
__device__ __align__(16) float  g_nsum[NF];
__device__ __align__(16) float  g_nsumsq[NF];

// ---------------- packed f32x2 helpers ----------------
typedef unsigned long long u64;
union F4U { float4 f; u64 u[2]; };

__device__ __forceinline__ u64 pack2(float a, float b) {
    u64 r; asm("mov.b64 %0, {%1, %2};" : "=l"(r) : "f"(a), "f"(b)); return r;
}
__device__ __forceinline__ void unpack2(u64 v, float& a, float& b) {
    asm("mov.b64 {%0, %1}, %2;" : "=f"(a), "=f"(b) : "l"(v));
}
__device__ __forceinline__ u64 fma2(u64 a, u64 b, u64 c) {
    u64 d; asm("fma.rn.f32x2 %0, %1, %2, %3;" : "=l"(d) : "l"(a), "l"(b), "l"(c)); return d;
}
__device__ __forceinline__ u64 add2(u64 a, u64 b) {
    u64 d; asm("add.rn.f32x2 %0, %1, %2;" : "=l"(d) : "l"(a), "l"(b)); return d;
}

__device__ __forceinline__ float sigf(float x) {
    return __fdividef(1.0f, 1.0f + __expf(-x));
}
__device__ __forceinline__ float spf(float x) {  // stable softplus
    return fmaxf(x, 0.0f) + __logf(1.0f + __expf(-fabsf(x)));
}

// cp.async 16B, with zero-fill when predicate is false
__device__ __forceinline__ void cp16(uint32_t smem_dst, const void* gsrc, bool pred) {
    if (pred)
        asm volatile("cp.async.cg.shared.global [%0], [%1], 16;" :: "r"(smem_dst), "l"(gsrc));
    else
        asm volatile("cp.async.cg.shared.global [%0], [%1], 16, 0;" :: "r"(smem_dst), "l"(gsrc));
}

// ================= K1: node projections h_src / h_dst (fp16 out) =================
// 4 nodes per warp share each W LDS; lane t owns channels [4t, 4t+4).
__global__ __launch_bounds__(256, 2)
void k_node_proj(const float* __restrict__ nf,
                 const float* __restrict__ Wsrc, const float* __restrict__ bsrc,
                 const float* __restrict__ Wdst, const float* __restrict__ bdst,
                 int N)
{
    extern __shared__ float sm[];
    float* smWs = sm;                 // 64*128 floats
    float* smWd = sm + NF * C;        // 64*128 floats
    float* smX  = sm + 2 * NF * C;    // 32 nodes * 64 floats

    int tid = threadIdx.x;
    for (int i = tid; i < NF * C; i += blockDim.x) { smWs[i] = Wsrc[i]; smWd[i] = Wdst[i]; }

    int warp = tid >> 5, lane = tid & 31;
    float4 bs4 = *(const float4*)(bsrc + 4 * lane);
    float4 bd4 = *(const float4*)(bdst + 4 * lane);
    u64 bs_lo = pack2(bs4.x, bs4.y), bs_hi = pack2(bs4.z, bs4.w);
    u64 bd_lo = pack2(bd4.x, bd4.y), bd_hi = pack2(bd4.z, bd4.w);

    const float4* Ws4 = (const float4*)smWs;
    const float4* Wd4 = (const float4*)smWd;
    const float4* nf4 = (const float4*)nf;

    for (int tile = blockIdx.x; tile * 32 < N; tile += gridDim.x) {
        __syncthreads();
        int nbase = tile * 32;
        for (int i = tid; i < 32 * (NF / 4); i += blockDim.x) {
            int n = nbase + (i >> 4);
            float4 v = make_float4(0.f, 0.f, 0.f, 0.f);
            if (n < N) v = nf4[(size_t)n * (NF / 4) + (i & 15)];
            ((float4*)smX)[i] = v;
        }
        __syncthreads();

        u64 as_lo[4], as_hi[4], ad_lo[4], ad_hi[4];
        #pragma unroll
        for (int t = 0; t < 4; ++t) { as_lo[t] = bs_lo; as_hi[t] = bs_hi; ad_lo[t] = bd_lo; ad_hi[t] = bd_hi; }

        const float4* X4 = (const float4*)(smX + (warp * 4) * NF);

        #pragma unroll
        for (int kk = 0; kk < NF / 4; ++kk) {
            float4 xv[4];
            #pragma unroll
            for (int t = 0; t < 4; ++t) xv[t] = X4[t * (NF / 4) + kk];
            #pragma unroll
            for (int j = 0; j < 4; ++j) {
                F4U ws; ws.f = Ws4[(kk * 4 + j) * 32 + lane];
                F4U wd; wd.f = Wd4[(kk * 4 + j) * 32 + lane];
                #pragma unroll
                for (int t = 0; t < 4; ++t) {
                    float xs = ((const float*)&xv[t])[j];
                    u64 xx = pack2(xs, xs);
                    as_lo[t] = fma2(xx, ws.u[0], as_lo[t]);
                    as_hi[t] = fma2(xx, ws.u[1], as_hi[t]);
                    ad_lo[t] = fma2(xx, wd.u[0], ad_lo[t]);
                    ad_hi[t] = fma2(xx, wd.u[1], ad_hi[t]);
                }
            }
        }

        #pragma unroll
        for (int t = 0; t < 4; ++t) {
            int n = nbase + warp * 4 + t;
            if (n < N) {
                float f0, f1, f2, f3;
                uint2 o;
                unpack2(as_lo[t], f0, f1); unpack2(as_hi[t], f2, f3);
                __half2 h01 = __floats2half2_rn(f0, f1), h23 = __floats2half2_rn(f2, f3);
                o.x = *(unsigned*)&h01; o.y = *(unsigned*)&h23;
                *(uint2*)(g_hsrc + (size_t)n * C + 4 * lane) = o;
                unpack2(ad_lo[t], f0, f1); unpack2(ad_hi[t], f2, f3);
                h01 = __floats2half2_rn(f0, f1); h23 = __floats2half2_rn(f2, f3);
                o.x = *(unsigned*)&h01; o.y = *(unsigned*)&h23;
                *(uint2*)(g_hdst + (size_t)n * C + 4 * lane) = o;
            }
        }
    }
}

// ================= K2: pipelined edge GEMM (register-resident W) -> m(fp16) + BN stats ==
// Tile = 32 edges. Warp owns 4 edges; lane t owns channels [4t,4t+4).
// W held entirely in registers (32 float4 per lane) — no W smem traffic in the loop.
__global__ __launch_bounds__(256)
void k_edge_pass1(const float* __restrict__ ef,
                  const float* __restrict__ We, const float* __restrict__ be,
                  const int* __restrict__ src, const int* __restrict__ dst,
                  int E)
{
    // dynamic smem: X 4 stages x 4KB | H 4 stages x 16KB(fp16)  = 80 KB
    extern __shared__ char dsmc[];
    float*  smX = (float*)dsmc;
    __half* smH = (__half*)(dsmc + STAGES * TILE_E * EF * 4);
    __shared__ int   smI[STAGES * 2 * TILE_E];   // per stage: [0..31]=src, [32..63]=dst
    __shared__ float smRed[2 * C];

    const int tid = threadIdx.x, warp = tid >> 5, lane = tid & 31;

    // ---- register-resident W: lane's 4 channels for every k ----
    F4U wreg[EF];
    #pragma unroll
    for (int r = 0; r < EF; ++r)
        wreg[r].f = *(const float4*)(We + r * C + 4 * lane);

    uint32_t smX_u32 = (uint32_t)__cvta_generic_to_shared(smX);
    uint32_t smH_u32 = (uint32_t)__cvta_generic_to_shared(smH);

    float4 b4 = *(const float4*)(be + 4 * lane);
    const u64 b_lo = pack2(b4.x, b4.y), b_hi = pack2(b4.z, b4.w);

    u64 s_lo = 0ull, s_hi = 0ull, q_lo = 0ull, q_hi = 0ull;

    const int ntiles = (E + TILE_E - 1) / TILE_E;

    auto tileOf = [&](int k) -> long { return (long)blockIdx.x + (long)k * gridDim.x; };

    auto ldg_idx = [&](long t) -> int {
        int v = 0;
        if (t < ntiles && tid < 64) {
            long e = t * TILE_E + (tid & 31);
            if (e < E) v = (tid < 32) ? src[e] : dst[e];
        }
        return v;
    };
    auto sts_idx = [&](int slot, int v) {
        if (tid < 64) smI[slot * 64 + tid] = v;
    };
    // one commit_group per call (empty group if out of range)
    auto issue_tile = [&](long t, int stage) {
        if (t < ntiles) {
            long ebase = t * TILE_E;
            {   // X: 256 chunks of 16B (32 edges * 128B)
                int c = tid, e = c >> 3, col = c & 7;
                bool p = (ebase + e) < E;
                cp16(smX_u32 + (uint32_t)(stage * TILE_E * EF + c * 4) * 4,
                     ef + (ebase + e) * EF + col * 4, p);
            }
            const int* I = smI + stage * 64;
            #pragma unroll
            for (int kq = 0; kq < 4; ++kq) {     // H: 1024 chunks (32 edges * 2 * 256B fp16)
                int c = tid + kq * 256;
                int e = c >> 5, r = c & 31, tb = r >> 4, col = r & 15;
                int node = I[tb * 32 + e];
                const __half* sp = (tb ? g_hdst : g_hsrc) + (size_t)node * C + col * 8;
                bool p = (ebase + e) < E;
                cp16(smH_u32 + (uint32_t)(stage * TILE_E * 256 + e * 256 + tb * 128 + col * 8) * 2,
                     sp, p);
            }
        }
        asm volatile("cp.async.commit_group;" ::: "memory");
    };

    // -------- prologue: indices for tiles 0..3, issue tiles 0..2 --------
    #pragma unroll
    for (int j = 0; j < STAGES; ++j) { int v = ldg_idx(tileOf(j)); sts_idx(j, v); }
    __syncthreads();
    issue_tile(tileOf(0), 0);
    issue_tile(tileOf(1), 1);
    issue_tile(tileOf(2), 2);

    // -------- main loop --------
    for (int k = 0;; ++k) {
        long t = tileOf(k);
        if (t >= ntiles) break;
        int stage = k & (STAGES - 1);

        issue_tile(tileOf(k + 3), (k + 3) & (STAGES - 1));   // 3 tiles ahead
        int vp = ldg_idx(tileOf(k + 4));                     // indices 4 ahead (reg-carried)
        asm volatile("cp.async.wait_group 3;" ::: "memory");
        __syncthreads();                                     // tile k data visible

        // ---- compute tile k ----
        const float4* X4 = (const float4*)(smX + stage * TILE_E * EF);
        const __half* Hs = smH + stage * TILE_E * 256;
        long ebase = t * TILE_E;
        int  ew    = warp * 4;

        u64 a_lo[4], a_hi[4];
        #pragma unroll
        for (int u = 0; u < 4; ++u) { a_lo[u] = b_lo; a_hi[u] = b_hi; }

        #pragma unroll
        for (int kk = 0; kk < EF / 4; ++kk) {
            #pragma unroll
            for (int u = 0; u < 4; ++u) {
                float4 xv = X4[(ew + u) * (EF / 4) + kk];   // broadcast LDS
                #pragma unroll
                for (int j = 0; j < 4; ++j) {
                    float xs = ((const float*)&xv)[j];
                    u64 xx = pack2(xs, xs);
                    a_lo[u] = fma2(xx, wreg[kk * 4 + j].u[0], a_lo[u]);
                    a_hi[u] = fma2(xx, wreg[kk * 4 + j].u[1], a_hi[u]);
                }
            }
        }

        #pragma unroll
        for (int u = 0; u < 4; ++u) {
            long e = ebase + ew + u;
            if (e < E) {
                uint2 hsv = *(const uint2*)(Hs + (ew + u) * 256 + lane * 4);
                uint2 hdv = *(const uint2*)(Hs + (ew + u) * 256 + 128 + lane * 4);
                float2 s0 = __half22float2(*(__half2*)&hsv.x);
                float2 s1 = __half22float2(*(__half2*)&hsv.y);
                float2 d0 = __half22float2(*(__half2*)&hdv.x);
                float2 d1 = __half22float2(*(__half2*)&hdv.y);
                u64 lo = add2(add2(a_lo[u], pack2(s0.x, s0.y)), pack2(d0.x, d0.y));
                u64 hi = add2(add2(a_hi[u], pack2(s1.x, s1.y)), pack2(d1.x, d1.y));
                float f0, f1, f2, f3;
                unpack2(lo, f0, f1); unpack2(hi, f2, f3);
                __half2 p0 = __floats2half2_rn(f0, f1);
                __half2 p1 = __floats2half2_rn(f2, f3);
                unsigned r0 = *(unsigned*)&p0, r1 = *(unsigned*)&p1;
                asm volatile("st.global.cs.v2.b32 [%0], {%1, %2};"
                             :: "l"(g_mh + (size_t)e * C + 4 * lane), "r"(r0), "r"(r1)
                             : "memory");
                s_lo = add2(s_lo, lo); s_hi = add2(s_hi, hi);
                q_lo = fma2(lo, lo, q_lo); q_hi = fma2(hi, hi, q_hi);
            }
        }

        sts_idx(k & (STAGES - 1), vp);   // indices for tile k+4 into freed slot
        __syncthreads();                 // protect smI + stage buffers for next iter
    }

    // -------- block-level BN-stat reduction --------
    __syncthreads();
    for (int i = tid; i < 2 * C; i += blockDim.x) smRed[i] = 0.0f;
    __syncthreads();
    float v0, v1, v2, v3;
    unpack2(s_lo, v0, v1); unpack2(s_hi, v2, v3);
    atomicAdd(&smRed[4 * lane + 0], v0); atomicAdd(&smRed[4 * lane + 1], v1);
    atomicAdd(&smRed[4 * lane + 2], v2); atomicAdd(&smRed[4 * lane + 3], v3);
    unpack2(q_lo, v0, v1); unpack2(q_hi, v2, v3);
    atomicAdd(&smRed[C + 4 * lane + 0], v0); atomicAdd(&smRed[C + 4 * lane + 1], v1);
    atomicAdd(&smRed[C + 4 * lane + 2], v2); atomicAdd(&smRed[C + 4 * lane + 3], v3);
    __syncthreads();
    if (tid < C) {
        atomicAdd(&g_sum[tid],   smRed[tid]);
        atomicAdd(&g_sumsq[tid], smRed[C + tid]);
    }
}

// ================= K3: finalize edge-BN scale/shift =================
__global__ void k_bn_m(const float* __restrict__ gamma, const float* __restrict__ beta, float invE)
{
    int t = threadIdx.x;  // 128 threads
    float mean = g_sum[t] * invE;
    float var  = fmaxf(g_sumsq[t] * invE - mean * mean, 0.0f);
    float s    = gamma[t] * rsqrtf(var + BN_EPS);
    g_bn_s[t] = s;
    g_bn_b[t] = beta[t] - mean * s;
}

// ================= K4: BN + sigmoid*softplus gate + scatter-add =================
// half-warp (16 lanes) per edge; lane-in-half h owns channels [4h, 4h+4). fp16 m.
__global__ void k_edge_pass2(const int* __restrict__ dst, int E)
{
    int lane = threadIdx.x & 31;
    int h    = lane & 15;
    int half = lane >> 4;
    long gw     = (long)blockIdx.x * (blockDim.x >> 5) + (threadIdx.x >> 5);
    long nwarps = (long)gridDim.x * (blockDim.x >> 5);

    float4 sA = *(const float4*)(g_bn_s + 4 * h);
    float4 bA = *(const float4*)(g_bn_b + 4 * h);
    float4 sB = *(const float4*)(g_bn_s + NF + 4 * h);
    float4 bB = *(const float4*)(g_bn_b + NF + 4 * h);

    for (long p = gw; p * 2 < E; p += nwarps) {
        long e = 2 * p + half;
        if (e < E) {
            int d = dst[e];
            const __half* pm = g_mh + (size_t)e * C + 4 * h;
            unsigned v0, v1, v2, v3;
            asm("ld.global.cs.v2.b32 {%0, %1}, [%2];" : "=r"(v0), "=r"(v1) : "l"(pm));
            asm("ld.global.cs.v2.b32 {%0, %1}, [%2];" : "=r"(v2), "=r"(v3) : "l"(pm + NF));
            float2 m1a = __half22float2(*(__half2*)&v0);
            float2 m1b = __half22float2(*(__half2*)&v1);
            float2 m2a = __half22float2(*(__half2*)&v2);
            float2 m2b = __half22float2(*(__half2*)&v3);
            float a0 = fmaf(m1a.x, sA.x, bA.x), a1 = fmaf(m1a.y, sA.y, bA.y);
            float a2 = fmaf(m1b.x, sA.z, bA.z), a3 = fmaf(m1b.y, sA.w, bA.w);
            float g0 = fmaf(m2a.x, sB.x, bB.x), g1 = fmaf(m2a.y, sB.y, bB.y);
            float g2 = fmaf(m2b.x, sB.z, bB.z), g3 = fmaf(m2b.y, sB.w, bB.w);
            float y0 = sigf(a0) * spf(g0);
            float y1 = sigf(a1) * spf(g1);
            float y2 = sigf(a2) * spf(g2);
            float y3 = sigf(a3) * spf(g3);
            float* pd = g_h + (size_t)d * NF + 4 * h;
            asm volatile("red.global.add.v4.f32 [%0], {%1, %2, %3, %4};"
                         :: "l"(pd), "f"(y0), "f"(y1), "f"(y2), "f"(y3) : "memory");
        }
    }
}

// ================= K5: node-BN statistics =================
__global__ void k_node_stats(int N)
{
    __shared__ float smS[NF], smQ[NF];
    int tid = threadIdx.x;
    if (tid < NF) { smS[tid] = 0.0f; smQ[tid] = 0.0f; }
    __syncthreads();
    float s = 0.0f, q = 0.0f;
    long total  = (long)N * NF;
    long stride = (long)gridDim.x * blockDim.x;   // multiple of 64
    for (long i = (long)blockIdx.x * blockDim.x + tid; i < total; i += stride) {
        float v = g_h[i];
        s += v; q += v * v;
    }
    int c = tid & 63;
    atomicAdd(&smS[c], s);
    atomicAdd(&smQ[c], q);
    __syncthreads();
    if (tid < NF) {
        atomicAdd(&g_nsum[tid],   smS[tid]);
        atomicAdd(&g_nsumsq[tid], smQ[tid]);
    }
}

// ================= K6: node BN + residual + softplus =================
__global__ void k_final(const float* __restrict__ nf,
                        const float* __restrict__ gamma, const float* __restrict__ beta,
                        float* __restrict__ out, int N)
{
    __shared__ float sS[NF], sB[NF];
    int tid = threadIdx.x;
    if (tid < NF) {
        float invN = 1.0f / (float)N;
        float mean = g_nsum[tid] * invN;
        float var  = fmaxf(g_nsumsq[tid] * invN - mean * mean, 0.0f);
        float s    = gamma[tid] * rsqrtf(var + BN_EPS);
        sS[tid] = s;
        sB[tid] = beta[tid] - mean * s;
    }
    __syncthreads();
    long total  = (long)N * NF;
    long stride = (long)gridDim.x * blockDim.x;   // multiple of 64
    int  c = tid & 63;
    float s = sS[c], b = sB[c];
    for (long i = (long)blockIdx.x * blockDim.x + tid; i < total; i += stride) {
        float x = nf[i] + fmaf(g_h[i], s, b);
        out[i]  = fmaxf(x, 0.0f) + __logf(1.0f + __expf(-fabsf(x)));
    }
}

// ================= launch =================
extern "C" void kernel_launch(void* const* d_in, const int* in_sizes, int n_in,
                              void* d_out, int out_size)
{
    const float* node_feats = (const float*)d_in[0];
    const float* edge_feats = (const float*)d_in[1];
    const float* W_src   = (const float*)d_in[2];
    const float* b_src   = (const float*)d_in[3];
    const float* W_dst   = (const float*)d_in[4];
    const float* b_dst   = (const float*)d_in[5];
    const float* W_edge  = (const float*)d_in[6];
    const float* b_edge  = (const float*)d_in[7];
    const float* gamma_m = (const float*)d_in[8];
    const float* beta_m  = (const float*)d_in[9];
    const float* gamma_n = (const float*)d_in[10];
    const float* beta_n  = (const float*)d_in[11];
    const int*   src     = (const int*)d_in[12];
    const int*   dst     = (const int*)d_in[13];

    int N = in_sizes[0] / NF;
    int E = in_sizes[12];

    void *ph, *psum, *psumsq, *pnsum, *pnsumsq;
    cudaGetSymbolAddress(&ph, g_h);
    cudaGetSymbolAddress(&psum, g_sum);
    cudaGetSymbolAddress(&psumsq, g_sumsq);
    cudaGetSymbolAddress(&pnsum, g_nsum);
    cudaGetSymbolAddress(&pnsumsq, g_nsumsq);
    cudaMemsetAsync(ph, 0, (size_t)N * NF * sizeof(float));
    cudaMemsetAsync(psum, 0, C * sizeof(float));
    cudaMemsetAsync(psumsq, 0, C * sizeof(float));
    cudaMemsetAsync(pnsum, 0, NF * sizeof(float));
    cudaMemsetAsync(pnsumsq, 0, NF * sizeof(float));

    int smem1 = (2 * NF * C + 32 * NF) * (int)sizeof(float);   // 72 KB
    cudaFuncSetAttribute(k_node_proj, cudaFuncAttributeMaxDynamicSharedMemorySize, smem1);

    // K2 dynamic smem: X 4x4KB + H 4x16KB = 80KB; W lives in registers
    int smem2 = STAGES * TILE_E * EF * 4 + STAGES * TILE_E * 256 * 2;
    cudaFuncSetAttribute(k_edge_pass1, cudaFuncAttributeMaxDynamicSharedMemorySize, smem2);

    k_node_proj<<<1184, 256, smem1>>>(node_feats, W_src, b_src, W_dst, b_dst, N);
    k_edge_pass1<<<148, 256, smem2>>>(edge_feats, W_edge, b_edge, src, dst, E);
    k_bn_m<<<1, 128>>>(gamma_m, beta_m, 1.0f / (float)E);
    k_edge_pass2<<<2368, 256>>>(dst, E);
    k_node_stats<<<512, 256>>>(N);
    k_final<<<512, 256>>>(node_feats, gamma_n, beta_n, (float*)d_out, N);
}

// round 16
// speedup vs baseline: 1.1729x; 1.1729x over previous
#include <cuda_runtime.h>
#include <cuda_fp16.h>
#include <stdint.h>

#define NF     64
#define C      128
#define EF     32
#define MAXN   100000
#define MAXE   1600000
#define BN_EPS 1e-5f
#define TILE_E 32
#define STAGES 4

// ---------------- scratch (device globals; no allocations) ----------------
__device__ __align__(16) __half g_hsrc[(size_t)MAXN * C];   // 25.6 MB (fp16)
__device__ __align__(16) __half g_hdst[(size_t)MAXN * C];   // 25.6 MB (fp16)
__device__ __align__(16) __half g_mh[(size_t)MAXE * C];     // 409.6 MB (fp16 m)
__device__ __align__(16) float  g_h[(size_t)MAXN * NF];     // 25.6 MB
__device__ __align__(16) float  g_sum[C];
__device__ __align__(16) float  g_sumsq[C];
__device__ __align__(16) float  g_bn_s[C];
__device__ __align__(16) float  g_bn_b[C];
__device__ __align__(16) float  g_nsum[NF];
__device__ __align__(16) float  g_nsumsq[NF];

// ---------------- packed f32x2 helpers ----------------
typedef unsigned long long u64;
union F4U { float4 f; u64 u[2]; };

__device__ __forceinline__ u64 pack2(float a, float b) {
    u64 r; asm("mov.b64 %0, {%1, %2};" : "=l"(r) : "f"(a), "f"(b)); return r;
}
__device__ __forceinline__ void unpack2(u64 v, float& a, float& b) {
    asm("mov.b64 {%0, %1}, %2;" : "=f"(a), "=f"(b) : "l"(v));
}
__device__ __forceinline__ u64 fma2(u64 a, u64 b, u64 c) {
    u64 d; asm("fma.rn.f32x2 %0, %1, %2, %3;" : "=l"(d) : "l"(a), "l"(b), "l"(c)); return d;
}
__device__ __forceinline__ u64 add2(u64 a, u64 b) {
    u64 d; asm("add.rn.f32x2 %0, %1, %2;" : "=l"(d) : "l"(a), "l"(b)); return d;
}

__device__ __forceinline__ float sigf(float x) {
    return __fdividef(1.0f, 1.0f + __expf(-x));
}
__device__ __forceinline__ float spf(float x) {  // stable softplus
    return fmaxf(x, 0.0f) + __logf(1.0f + __expf(-fabsf(x)));
}

// cp.async 16B, with zero-fill when predicate is false
__device__ __forceinline__ void cp16(uint32_t smem_dst, const void* gsrc, bool pred) {
    if (pred)
        asm volatile("cp.async.cg.shared.global [%0], [%1], 16;" :: "r"(smem_dst), "l"(gsrc));
    else
        asm volatile("cp.async.cg.shared.global [%0], [%1], 16, 0;" :: "r"(smem_dst), "l"(gsrc));
}

// ================= K1: node projections h_src / h_dst (fp16 out) =================
// 4 nodes per warp share each W LDS; lane t owns channels [4t, 4t+4).
__global__ __launch_bounds__(256, 2)
void k_node_proj(const float* __restrict__ nf,
                 const float* __restrict__ Wsrc, const float* __restrict__ bsrc,
                 const float* __restrict__ Wdst, const float* __restrict__ bdst,
                 int N)
{
    extern __shared__ float sm[];
    float* smWs = sm;                 // 64*128 floats
    float* smWd = sm + NF * C;        // 64*128 floats
    float* smX  = sm + 2 * NF * C;    // 32 nodes * 64 floats

    int tid = threadIdx.x;
    for (int i = tid; i < NF * C; i += blockDim.x) { smWs[i] = Wsrc[i]; smWd[i] = Wdst[i]; }

    int warp = tid >> 5, lane = tid & 31;
    float4 bs4 = *(const float4*)(bsrc + 4 * lane);
    float4 bd4 = *(const float4*)(bdst + 4 * lane);
    u64 bs_lo = pack2(bs4.x, bs4.y), bs_hi = pack2(bs4.z, bs4.w);
    u64 bd_lo = pack2(bd4.x, bd4.y), bd_hi = pack2(bd4.z, bd4.w);

    const float4* Ws4 = (const float4*)smWs;
    const float4* Wd4 = (const float4*)smWd;
    const float4* nf4 = (const float4*)nf;

    for (int tile = blockIdx.x; tile * 32 < N; tile += gridDim.x) {
        __syncthreads();
        int nbase = tile * 32;
        for (int i = tid; i < 32 * (NF / 4); i += blockDim.x) {
            int n = nbase + (i >> 4);
            float4 v = make_float4(0.f, 0.f, 0.f, 0.f);
            if (n < N) v = nf4[(size_t)n * (NF / 4) + (i & 15)];
            ((float4*)smX)[i] = v;
        }
        __syncthreads();

        u64 as_lo[4], as_hi[4], ad_lo[4], ad_hi[4];
        #pragma unroll
        for (int t = 0; t < 4; ++t) { as_lo[t] = bs_lo; as_hi[t] = bs_hi; ad_lo[t] = bd_lo; ad_hi[t] = bd_hi; }

        const float4* X4 = (const float4*)(smX + (warp * 4) * NF);

        #pragma unroll
        for (int kk = 0; kk < NF / 4; ++kk) {
            float4 xv[4];
            #pragma unroll
            for (int t = 0; t < 4; ++t) xv[t] = X4[t * (NF / 4) + kk];
            #pragma unroll
            for (int j = 0; j < 4; ++j) {
                F4U ws; ws.f = Ws4[(kk * 4 + j) * 32 + lane];
                F4U wd; wd.f = Wd4[(kk * 4 + j) * 32 + lane];
                #pragma unroll
                for (int t = 0; t < 4; ++t) {
                    float xs = ((const float*)&xv[t])[j];
                    u64 xx = pack2(xs, xs);
                    as_lo[t] = fma2(xx, ws.u[0], as_lo[t]);
                    as_hi[t] = fma2(xx, ws.u[1], as_hi[t]);
                    ad_lo[t] = fma2(xx, wd.u[0], ad_lo[t]);
                    ad_hi[t] = fma2(xx, wd.u[1], ad_hi[t]);
                }
            }
        }

        #pragma unroll
        for (int t = 0; t < 4; ++t) {
            int n = nbase + warp * 4 + t;
            if (n < N) {
                float f0, f1, f2, f3;
                uint2 o;
                unpack2(as_lo[t], f0, f1); unpack2(as_hi[t], f2, f3);
                __half2 h01 = __floats2half2_rn(f0, f1), h23 = __floats2half2_rn(f2, f3);
                o.x = *(unsigned*)&h01; o.y = *(unsigned*)&h23;
                *(uint2*)(g_hsrc + (size_t)n * C + 4 * lane) = o;
                unpack2(ad_lo[t], f0, f1); unpack2(ad_hi[t], f2, f3);
                h01 = __floats2half2_rn(f0, f1); h23 = __floats2half2_rn(f2, f3);
                o.x = *(unsigned*)&h01; o.y = *(unsigned*)&h23;
                *(uint2*)(g_hdst + (size_t)n * C + 4 * lane) = o;
            }
        }
    }
}

// ================= K2: pipelined edge GEMM, split-channel register W ==================
// Tile = 32 edges. Warp pair p = warp>>1, hf = warp&1: warp owns 8 edges x 64 channels.
// Lane owns 2 channels (c = hf*64 + 2*lane); W = 32 u64 registers per lane.
__global__ __launch_bounds__(256, 2)
void k_edge_pass1(const float* __restrict__ ef,
                  const float* __restrict__ We, const float* __restrict__ be,
                  const int* __restrict__ src, const int* __restrict__ dst,
                  int E)
{
    // dynamic smem: X 4 stages x 4KB | H 4 stages x 16KB(fp16)  = 80 KB
    extern __shared__ char dsmc[];
    float*  smX = (float*)dsmc;
    __half* smH = (__half*)(dsmc + STAGES * TILE_E * EF * 4);
    __shared__ int   smI[STAGES * 2 * TILE_E];   // per stage: [0..31]=src, [32..63]=dst
    __shared__ float smRed[2 * C];

    const int tid = threadIdx.x, warp = tid >> 5, lane = tid & 31;
    const int pair = warp >> 1, hf = warp & 1;
    const int ch = hf * 64 + 2 * lane;           // this lane's 2 channels
    const int ew = pair * 8;                     // warp's 8 edges within tile

    // ---- register-resident W: 2 channels x 32 k = 32 u64 ----
    u64 wreg[EF];
    #pragma unroll
    for (int r = 0; r < EF; ++r) {
        float2 wv = *(const float2*)(We + r * C + ch);
        wreg[r] = pack2(wv.x, wv.y);
    }
    float2 bb = *(const float2*)(be + ch);
    const u64 bias = pack2(bb.x, bb.y);

    uint32_t smX_u32 = (uint32_t)__cvta_generic_to_shared(smX);
    uint32_t smH_u32 = (uint32_t)__cvta_generic_to_shared(smH);

    u64 s_acc = 0ull, q_acc = 0ull;

    const int ntiles = (E + TILE_E - 1) / TILE_E;

    auto tileOf = [&](int k) -> long { return (long)blockIdx.x + (long)k * gridDim.x; };

    auto ldg_idx = [&](long t) -> int {
        int v = 0;
        if (t < ntiles && tid < 64) {
            long e = t * TILE_E + (tid & 31);
            if (e < E) v = (tid < 32) ? src[e] : dst[e];
        }
        return v;
    };
    auto sts_idx = [&](int slot, int v) {
        if (tid < 64) smI[slot * 64 + tid] = v;
    };
    // one commit_group per call (empty group if out of range)
    auto issue_tile = [&](long t, int stage) {
        if (t < ntiles) {
            long ebase = t * TILE_E;
            {   // X: 256 chunks of 16B (32 edges * 128B)
                int c = tid, e = c >> 3, col = c & 7;
                bool p = (ebase + e) < E;
                cp16(smX_u32 + (uint32_t)(stage * TILE_E * EF + c * 4) * 4,
                     ef + (ebase + e) * EF + col * 4, p);
            }
            const int* I = smI + stage * 64;
            #pragma unroll
            for (int kq = 0; kq < 4; ++kq) {     // H: 1024 chunks (32 edges * 2 * 256B fp16)
                int c = tid + kq * 256;
                int e = c >> 5, r = c & 31, tb = r >> 4, col = r & 15;
                int node = I[tb * 32 + e];
                const __half* sp = (tb ? g_hdst : g_hsrc) + (size_t)node * C + col * 8;
                bool p = (ebase + e) < E;
                cp16(smH_u32 + (uint32_t)(stage * TILE_E * 256 + e * 256 + tb * 128 + col * 8) * 2,
                     sp, p);
            }
        }
        asm volatile("cp.async.commit_group;" ::: "memory");
    };

    // -------- prologue: indices for tiles 0..3, issue tiles 0..2 --------
    #pragma unroll
    for (int j = 0; j < STAGES; ++j) { int v = ldg_idx(tileOf(j)); sts_idx(j, v); }
    __syncthreads();
    issue_tile(tileOf(0), 0);
    issue_tile(tileOf(1), 1);
    issue_tile(tileOf(2), 2);

    // -------- main loop --------
    for (int k = 0;; ++k) {
        long t = tileOf(k);
        if (t >= ntiles) break;
        int stage = k & (STAGES - 1);

        issue_tile(tileOf(k + 3), (k + 3) & (STAGES - 1));   // 3 tiles ahead
        int vp = ldg_idx(tileOf(k + 4));                     // indices 4 ahead (reg-carried)
        asm volatile("cp.async.wait_group 3;" ::: "memory");
        __syncthreads();                                     // tile k data visible

        // ---- compute tile k: 8 edges x 2 channels per lane ----
        const float4* X4 = (const float4*)(smX + stage * TILE_E * EF);
        const __half* Hs = smH + stage * TILE_E * 256;
        long ebase = t * TILE_E;

        u64 acc[8];
        #pragma unroll
        for (int u = 0; u < 8; ++u) acc[u] = bias;

        #pragma unroll
        for (int kk = 0; kk < EF / 4; ++kk) {
            #pragma unroll
            for (int u = 0; u < 8; ++u) {
                float4 xv = X4[(ew + u) * (EF / 4) + kk];   // broadcast LDS
                #pragma unroll
                for (int j = 0; j < 4; ++j) {
                    float xs = ((const float*)&xv)[j];
                    acc[u] = fma2(pack2(xs, xs), wreg[kk * 4 + j], acc[u]);
                }
            }
        }

        #pragma unroll
        for (int u = 0; u < 8; ++u) {
            long e = ebase + ew + u;
            if (e < E) {
                unsigned hsv = *(const unsigned*)(Hs + (ew + u) * 256 + ch);
                unsigned hdv = *(const unsigned*)(Hs + (ew + u) * 256 + 128 + ch);
                float2 fs = __half22float2(*(__half2*)&hsv);
                float2 fd = __half22float2(*(__half2*)&hdv);
                u64 m = add2(add2(acc[u], pack2(fs.x, fs.y)), pack2(fd.x, fd.y));
                float f0, f1;
                unpack2(m, f0, f1);
                __half2 p = __floats2half2_rn(f0, f1);
                unsigned pr = *(unsigned*)&p;
                asm volatile("st.global.cs.b32 [%0], %1;"
                             :: "l"(g_mh + (size_t)e * C + ch), "r"(pr) : "memory");
                s_acc = add2(s_acc, m);
                q_acc = fma2(m, m, q_acc);
            }
        }

        sts_idx(k & (STAGES - 1), vp);   // indices for tile k+4 into freed slot
        __syncthreads();                 // protect smI + stage buffers for next iter
    }

    // -------- block-level BN-stat reduction --------
    __syncthreads();
    for (int i = tid; i < 2 * C; i += blockDim.x) smRed[i] = 0.0f;
    __syncthreads();
    float v0, v1;
    unpack2(s_acc, v0, v1);
    atomicAdd(&smRed[ch], v0); atomicAdd(&smRed[ch + 1], v1);
    unpack2(q_acc, v0, v1);
    atomicAdd(&smRed[C + ch], v0); atomicAdd(&smRed[C + ch + 1], v1);
    __syncthreads();
    if (tid < C) {
        atomicAdd(&g_sum[tid],   smRed[tid]);
        atomicAdd(&g_sumsq[tid], smRed[C + tid]);
    }
}

// ================= K3: finalize edge-BN scale/shift =================
__global__ void k_bn_m(const float* __restrict__ gamma, const float* __restrict__ beta, float invE)
{
    int t = threadIdx.x;  // 128 threads
    float mean = g_sum[t] * invE;
    float var  = fmaxf(g_sumsq[t] * invE - mean * mean, 0.0f);
    float s    = gamma[t] * rsqrtf(var + BN_EPS);
    g_bn_s[t] = s;
    g_bn_b[t] = beta[t] - mean * s;
}

// ================= K4: BN + sigmoid*softplus gate + scatter-add =================
// half-warp (16 lanes) per edge; lane-in-half h owns channels [4h, 4h+4). fp16 m.
__global__ void k_edge_pass2(const int* __restrict__ dst, int E)
{
    int lane = threadIdx.x & 31;
    int h    = lane & 15;
    int half = lane >> 4;
    long gw     = (long)blockIdx.x * (blockDim.x >> 5) + (threadIdx.x >> 5);
    long nwarps = (long)gridDim.x * (blockDim.x >> 5);

    float4 sA = *(const float4*)(g_bn_s + 4 * h);
    float4 bA = *(const float4*)(g_bn_b + 4 * h);
    float4 sB = *(const float4*)(g_bn_s + NF + 4 * h);
    float4 bB = *(const float4*)(g_bn_b + NF + 4 * h);

    for (long p = gw; p * 2 < E; p += nwarps) {
        long e = 2 * p + half;
        if (e < E) {
            int d = dst[e];
            const __half* pm = g_mh + (size_t)e * C + 4 * h;
            unsigned v0, v1, v2, v3;
            asm("ld.global.cs.v2.b32 {%0, %1}, [%2];" : "=r"(v0), "=r"(v1) : "l"(pm));
            asm("ld.global.cs.v2.b32 {%0, %1}, [%2];" : "=r"(v2), "=r"(v3) : "l"(pm + NF));
            float2 m1a = __half22float2(*(__half2*)&v0);
            float2 m1b = __half22float2(*(__half2*)&v1);
            float2 m2a = __half22float2(*(__half2*)&v2);
            float2 m2b = __half22float2(*(__half2*)&v3);
            float a0 = fmaf(m1a.x, sA.x, bA.x), a1 = fmaf(m1a.y, sA.y, bA.y);
            float a2 = fmaf(m1b.x, sA.z, bA.z), a3 = fmaf(m1b.y, sA.w, bA.w);
            float g0 = fmaf(m2a.x, sB.x, bB.x), g1 = fmaf(m2a.y, sB.y, bB.y);
            float g2 = fmaf(m2b.x, sB.z, bB.z), g3 = fmaf(m2b.y, sB.w, bB.w);
            float y0 = sigf(a0) * spf(g0);
            float y1 = sigf(a1) * spf(g1);
            float y2 = sigf(a2) * spf(g2);
            float y3 = sigf(a3) * spf(g3);
            float* pd = g_h + (size_t)d * NF + 4 * h;
            asm volatile("red.global.add.v4.f32 [%0], {%1, %2, %3, %4};"
                         :: "l"(pd), "f"(y0), "f"(y1), "f"(y2), "f"(y3) : "memory");
        }
    }
}

// ================= K5: node-BN statistics =================
__global__ void k_node_stats(int N)
{
    __shared__ float smS[NF], smQ[NF];
    int tid = threadIdx.x;
    if (tid < NF) { smS[tid] = 0.0f; smQ[tid] = 0.0f; }
    __syncthreads();
    float s = 0.0f, q = 0.0f;
    long total  = (long)N * NF;
    long stride = (long)gridDim.x * blockDim.x;   // multiple of 64
    for (long i = (long)blockIdx.x * blockDim.x + tid; i < total; i += stride) {
        float v = g_h[i];
        s += v; q += v * v;
    }
    int c = tid & 63;
    atomicAdd(&smS[c], s);
    atomicAdd(&smQ[c], q);
    __syncthreads();
    if (tid < NF) {
        atomicAdd(&g_nsum[tid],   smS[tid]);
        atomicAdd(&g_nsumsq[tid], smQ[tid]);
    }
}

// ================= K6: node BN + residual + softplus =================
__global__ void k_final(const float* __restrict__ nf,
                        const float* __restrict__ gamma, const float* __restrict__ beta,
                        float* __restrict__ out, int N)
{
    __shared__ float sS[NF], sB[NF];
    int tid = threadIdx.x;
    if (tid < NF) {
        float invN = 1.0f / (float)N;
        float mean = g_nsum[tid] * invN;
        float var  = fmaxf(g_nsumsq[tid] * invN - mean * mean, 0.0f);
        float s    = gamma[tid] * rsqrtf(var + BN_EPS);
        sS[tid] = s;
        sB[tid] = beta[tid] - mean * s;
    }
    __syncthreads();
    long total  = (long)N * NF;
    long stride = (long)gridDim.x * blockDim.x;   // multiple of 64
    int  c = tid & 63;
    float s = sS[c], b = sB[c];
    for (long i = (long)blockIdx.x * blockDim.x + tid; i < total; i += stride) {
        float x = nf[i] + fmaf(g_h[i], s, b);
        out[i]  = fmaxf(x, 0.0f) + __logf(1.0f + __expf(-fabsf(x)));
    }
}

// ================= launch =================
extern "C" void kernel_launch(void* const* d_in, const int* in_sizes, int n_in,
                              void* d_out, int out_size)
{
    const float* node_feats = (const float*)d_in[0];
    const float* edge_feats = (const float*)d_in[1];
    const float* W_src   = (const float*)d_in[2];
    const float* b_src   = (const float*)d_in[3];
    const float* W_dst   = (const float*)d_in[4];
    const float* b_dst   = (const float*)d_in[5];
    const float* W_edge  = (const float*)d_in[6];
    const float* b_edge  = (const float*)d_in[7];
    const float* gamma_m = (const float*)d_in[8];
    const float* beta_m  = (const float*)d_in[9];
    const float* gamma_n = (const float*)d_in[10];
    const float* beta_n  = (const float*)d_in[11];
    const int*   src     = (const int*)d_in[12];
    const int*   dst     = (const int*)d_in[13];

    int N = in_sizes[0] / NF;
    int E = in_sizes[12];

    void *ph, *psum, *psumsq, *pnsum, *pnsumsq;
    cudaGetSymbolAddress(&ph, g_h);
    cudaGetSymbolAddress(&psum, g_sum);
    cudaGetSymbolAddress(&psumsq, g_sumsq);
    cudaGetSymbolAddress(&pnsum, g_nsum);
    cudaGetSymbolAddress(&pnsumsq, g_nsumsq);
    cudaMemsetAsync(ph, 0, (size_t)N * NF * sizeof(float));
    cudaMemsetAsync(psum, 0, C * sizeof(float));
    cudaMemsetAsync(psumsq, 0, C * sizeof(float));
    cudaMemsetAsync(pnsum, 0, NF * sizeof(float));
    cudaMemsetAsync(pnsumsq, 0, NF * sizeof(float));

    int smem1 = (2 * NF * C + 32 * NF) * (int)sizeof(float);   // 72 KB
    cudaFuncSetAttribute(k_node_proj, cudaFuncAttributeMaxDynamicSharedMemorySize, smem1);

    // K2 dynamic smem: X 4x4KB + H 4x16KB = 80KB; W lives in registers (2ch/lane)
    int smem2 = STAGES * TILE_E * EF * 4 + STAGES * TILE_E * 256 * 2;
    cudaFuncSetAttribute(k_edge_pass1, cudaFuncAttributeMaxDynamicSharedMemorySize, smem2);

    k_node_proj<<<1184, 256, smem1>>>(node_feats, W_src, b_src, W_dst, b_dst, N);
    k_edge_pass1<<<296, 256, smem2>>>(edge_feats, W_edge, b_edge, src, dst, E);
    k_bn_m<<<1, 128>>>(gamma_m, beta_m, 1.0f / (float)E);
    k_edge_pass2<<<2368, 256>>>(dst, E);
    k_node_stats<<<512, 256>>>(N);
    k_final<<<512, 256>>>(node_feats, gamma_n, beta_n, (float*)d_out, N);
}

// round 17
// speedup vs baseline: 1.2377x; 1.0553x over previous
#include <cuda_runtime.h>
#include <cuda_fp16.h>
#include <stdint.h>

#define NF     64
#define C      128
#define EF     32
#define MAXN   100000
#define MAXE   1600000
#define BN_EPS 1e-5f
#define TILE_E 32
#define STAGES 4

// ---------------- scratch (device globals; no allocations) ----------------
__device__ __align__(16) __half g_hsrc[(size_t)MAXN * C];   // 25.6 MB (fp16)
__device__ __align__(16) __half g_hdst[(size_t)MAXN * C];   // 25.6 MB (fp16)
__device__ __align__(16) __half g_mh[(size_t)MAXE * C];     // 409.6 MB (fp16 m)
__device__ __align__(16) float  g_h[(size_t)MAXN * NF];     // 25.6 MB
__device__ __align__(16) float  g_sum[C];
__device__ __align__(16) float  g_sumsq[C];
__device__ __align__(16) float  g_bn_s[C];
__device__ __align__(16) float  g_bn_b[C];
__device__ __align__(16) float  g_nsum[NF];
__device__ __align__(16) float  g_nsumsq[NF];

// ---------------- packed f32x2 helpers ----------------
typedef unsigned long long u64;
union F4U { float4 f; u64 u[2]; };

__device__ __forceinline__ u64 pack2(float a, float b) {
    u64 r; asm("mov.b64 %0, {%1, %2};" : "=l"(r) : "f"(a), "f"(b)); return r;
}
__device__ __forceinline__ void unpack2(u64 v, float& a, float& b) {
    asm("mov.b64 {%0, %1}, %2;" : "=f"(a), "=f"(b) : "l"(v));
}
__device__ __forceinline__ u64 fma2(u64 a, u64 b, u64 c) {
    u64 d; asm("fma.rn.f32x2 %0, %1, %2, %3;" : "=l"(d) : "l"(a), "l"(b), "l"(c)); return d;
}
__device__ __forceinline__ u64 add2(u64 a, u64 b) {
    u64 d; asm("add.rn.f32x2 %0, %1, %2;" : "=l"(d) : "l"(a), "l"(b)); return d;
}

__device__ __forceinline__ float sigf(float x) {
    return __fdividef(1.0f, 1.0f + __expf(-x));
}
__device__ __forceinline__ float spf(float x) {  // stable softplus
    return fmaxf(x, 0.0f) + __logf(1.0f + __expf(-fabsf(x)));
}

// cache policies
__device__ __forceinline__ u64 pol_evict_last() {
    u64 p; asm("createpolicy.fractional.L2::evict_last.b64 %0, 1.0;" : "=l"(p)); return p;
}
__device__ __forceinline__ u64 pol_evict_first() {
    u64 p; asm("createpolicy.fractional.L2::evict_first.b64 %0, 1.0;" : "=l"(p)); return p;
}

// cp.async 16B with cache policy; zero-fill when predicate is false
__device__ __forceinline__ void cp16p(uint32_t smem_dst, const void* gsrc, bool pred, u64 pol) {
    if (pred)
        asm volatile("cp.async.cg.shared.global.L2::cache_hint [%0], [%1], 16, %2;"
                     :: "r"(smem_dst), "l"(gsrc), "l"(pol));
    else
        asm volatile("cp.async.cg.shared.global [%0], [%1], 16, 0;" :: "r"(smem_dst), "l"(gsrc));
}

// ================= K1: node projections h_src / h_dst (fp16 out) =================
// 4 nodes per warp share each W LDS; lane t owns channels [4t, 4t+4).
__global__ __launch_bounds__(256, 2)
void k_node_proj(const float* __restrict__ nf,
                 const float* __restrict__ Wsrc, const float* __restrict__ bsrc,
                 const float* __restrict__ Wdst, const float* __restrict__ bdst,
                 int N)
{
    extern __shared__ float sm[];
    float* smWs = sm;                 // 64*128 floats
    float* smWd = sm + NF * C;        // 64*128 floats
    float* smX  = sm + 2 * NF * C;    // 32 nodes * 64 floats

    int tid = threadIdx.x;
    for (int i = tid; i < NF * C; i += blockDim.x) { smWs[i] = Wsrc[i]; smWd[i] = Wdst[i]; }

    int warp = tid >> 5, lane = tid & 31;
    float4 bs4 = *(const float4*)(bsrc + 4 * lane);
    float4 bd4 = *(const float4*)(bdst + 4 * lane);
    u64 bs_lo = pack2(bs4.x, bs4.y), bs_hi = pack2(bs4.z, bs4.w);
    u64 bd_lo = pack2(bd4.x, bd4.y), bd_hi = pack2(bd4.z, bd4.w);

    const float4* Ws4 = (const float4*)smWs;
    const float4* Wd4 = (const float4*)smWd;
    const float4* nf4 = (const float4*)nf;

    for (int tile = blockIdx.x; tile * 32 < N; tile += gridDim.x) {
        __syncthreads();
        int nbase = tile * 32;
        for (int i = tid; i < 32 * (NF / 4); i += blockDim.x) {
            int n = nbase + (i >> 4);
            float4 v = make_float4(0.f, 0.f, 0.f, 0.f);
            if (n < N) v = nf4[(size_t)n * (NF / 4) + (i & 15)];
            ((float4*)smX)[i] = v;
        }
        __syncthreads();

        u64 as_lo[4], as_hi[4], ad_lo[4], ad_hi[4];
        #pragma unroll
        for (int t = 0; t < 4; ++t) { as_lo[t] = bs_lo; as_hi[t] = bs_hi; ad_lo[t] = bd_lo; ad_hi[t] = bd_hi; }

        const float4* X4 = (const float4*)(smX + (warp * 4) * NF);

        #pragma unroll
        for (int kk = 0; kk < NF / 4; ++kk) {
            float4 xv[4];
            #pragma unroll
            for (int t = 0; t < 4; ++t) xv[t] = X4[t * (NF / 4) + kk];
            #pragma unroll
            for (int j = 0; j < 4; ++j) {
                F4U ws; ws.f = Ws4[(kk * 4 + j) * 32 + lane];
                F4U wd; wd.f = Wd4[(kk * 4 + j) * 32 + lane];
                #pragma unroll
                for (int t = 0; t < 4; ++t) {
                    float xs = ((const float*)&xv[t])[j];
                    u64 xx = pack2(xs, xs);
                    as_lo[t] = fma2(xx, ws.u[0], as_lo[t]);
                    as_hi[t] = fma2(xx, ws.u[1], as_hi[t]);
                    ad_lo[t] = fma2(xx, wd.u[0], ad_lo[t]);
                    ad_hi[t] = fma2(xx, wd.u[1], ad_hi[t]);
                }
            }
        }

        #pragma unroll
        for (int t = 0; t < 4; ++t) {
            int n = nbase + warp * 4 + t;
            if (n < N) {
                float f0, f1, f2, f3;
                uint2 o;
                unpack2(as_lo[t], f0, f1); unpack2(as_hi[t], f2, f3);
                __half2 h01 = __floats2half2_rn(f0, f1), h23 = __floats2half2_rn(f2, f3);
                o.x = *(unsigned*)&h01; o.y = *(unsigned*)&h23;
                *(uint2*)(g_hsrc + (size_t)n * C + 4 * lane) = o;
                unpack2(ad_lo[t], f0, f1); unpack2(ad_hi[t], f2, f3);
                h01 = __floats2half2_rn(f0, f1); h23 = __floats2half2_rn(f2, f3);
                o.x = *(unsigned*)&h01; o.y = *(unsigned*)&h23;
                *(uint2*)(g_hdst + (size_t)n * C + 4 * lane) = o;
            }
        }
    }
}

// ================= K2: pipelined edge GEMM + fp16 gathers -> m(fp16) + BN stats ========
// Tile = 32 edges, 4 cp.async stages, ONE barrier per tile. Warp owns 4 edges;
// lane t owns channels [4t,4t+4). W in smem; gathers pinned in L2 via evict_last.
__global__ __launch_bounds__(256, 2)
void k_edge_pass1(const float* __restrict__ ef,
                  const float* __restrict__ We, const float* __restrict__ be,
                  const int* __restrict__ src, const int* __restrict__ dst,
                  int E)
{
    // dynamic smem: W 16KB | X 4 stages x 4KB | H 4 stages x 16KB(fp16)  = 96 KB
    extern __shared__ char dsmc[];
    float*  smW = (float*)dsmc;
    float*  smX = (float*)(dsmc + 16384);
    __half* smH = (__half*)(dsmc + 16384 + STAGES * TILE_E * EF * 4);
    __shared__ int   smI[STAGES * 2 * TILE_E];   // slot s: indices for tile ≡ s (mod 4)
    __shared__ float smRed[2 * C];

    const int tid = threadIdx.x, warp = tid >> 5, lane = tid & 31;

    for (int i = tid; i < EF * C; i += blockDim.x) smW[i] = We[i];

    const u64 polL = pol_evict_last();
    const u64 polF = pol_evict_first();

    uint32_t smX_u32 = (uint32_t)__cvta_generic_to_shared(smX);
    uint32_t smH_u32 = (uint32_t)__cvta_generic_to_shared(smH);

    float4 b4 = *(const float4*)(be + 4 * lane);
    const u64 b_lo = pack2(b4.x, b4.y), b_hi = pack2(b4.z, b4.w);

    u64 s_lo = 0ull, s_hi = 0ull, q_lo = 0ull, q_hi = 0ull;

    const int ntiles = (E + TILE_E - 1) / TILE_E;

    auto tileOf = [&](int k) -> long { return (long)blockIdx.x + (long)k * gridDim.x; };

    auto ldg_idx = [&](long t) -> int {
        int v = 0;
        if (t < ntiles && tid < 64) {
            long e = t * TILE_E + (tid & 31);
            if (e < E) v = (tid < 32) ? src[e] : dst[e];
        }
        return v;
    };
    auto sts_idx = [&](int slot, int v) {
        if (tid < 64) smI[slot * 64 + tid] = v;
    };
    // one commit_group per call (empty group if out of range)
    auto issue_tile = [&](long t, int stage) {
        if (t < ntiles) {
            long ebase = t * TILE_E;
            {   // X: 256 chunks of 16B (32 edges * 128B), streaming -> evict_first
                int c = tid, e = c >> 3, col = c & 7;
                bool p = (ebase + e) < E;
                cp16p(smX_u32 + (uint32_t)(stage * TILE_E * EF + c * 4) * 4,
                      ef + (ebase + e) * EF + col * 4, p, polF);
            }
            const int* I = smI + stage * 64;
            #pragma unroll
            for (int kq = 0; kq < 4; ++kq) {     // H: 1024 chunks (32 edges * 2 * 256B fp16)
                int c = tid + kq * 256;
                int e = c >> 5, r = c & 31, tb = r >> 4, col = r & 15;
                int node = I[tb * 32 + e];
                const __half* sp = (tb ? g_hdst : g_hsrc) + (size_t)node * C + col * 8;
                bool p = (ebase + e) < E;
                cp16p(smH_u32 + (uint32_t)(stage * TILE_E * 256 + e * 256 + tb * 128 + col * 8) * 2,
                      sp, p, polL);
            }
        }
        asm volatile("cp.async.commit_group;" ::: "memory");
    };

    // -------- prologue: indices for tiles 0..3 in slots 0..3; issue tiles 0..2 --------
    #pragma unroll
    for (int j = 0; j < STAGES; ++j) { int v = ldg_idx(tileOf(j)); sts_idx(j, v); }
    __syncthreads();
    issue_tile(tileOf(0), 0);
    issue_tile(tileOf(1), 1);
    issue_tile(tileOf(2), 2);

    // -------- main loop: ONE barrier per tile --------
    for (int k = 0;; ++k) {
        long t = tileOf(k);
        if (t >= ntiles) break;
        int stage = k & (STAGES - 1);

        asm volatile("cp.async.wait_group 2;" ::: "memory");   // my copies for tile k done
        __syncthreads();                                       // everyone's done; smI writes visible

        int vp = ldg_idx(tileOf(k + 4));                       // indices 4 ahead (reg-carried)
        issue_tile(tileOf(k + 3), (k + 3) & (STAGES - 1));     // overwrites stage (k-1)&3: safe

        // ---- compute tile k ----
        const float4* W4 = (const float4*)smW;
        const float4* X4 = (const float4*)(smX + stage * TILE_E * EF);
        const __half* Hs = smH + stage * TILE_E * 256;
        long ebase = t * TILE_E;
        int  ew    = warp * 4;

        u64 a_lo[4], a_hi[4];
        #pragma unroll
        for (int u = 0; u < 4; ++u) { a_lo[u] = b_lo; a_hi[u] = b_hi; }

        #pragma unroll
        for (int kk = 0; kk < EF / 4; ++kk) {
            F4U w[4];
            #pragma unroll
            for (int j = 0; j < 4; ++j) w[j].f = W4[(kk * 4 + j) * 32 + lane];
            #pragma unroll
            for (int u = 0; u < 4; ++u) {
                float4 xv = X4[(ew + u) * (EF / 4) + kk];   // broadcast LDS
                #pragma unroll
                for (int j = 0; j < 4; ++j) {
                    float xs = ((const float*)&xv)[j];
                    u64 xx = pack2(xs, xs);
                    a_lo[u] = fma2(xx, w[j].u[0], a_lo[u]);
                    a_hi[u] = fma2(xx, w[j].u[1], a_hi[u]);
                }
            }
        }

        #pragma unroll
        for (int u = 0; u < 4; ++u) {
            long e = ebase + ew + u;
            if (e < E) {
                uint2 hsv = *(const uint2*)(Hs + (ew + u) * 256 + lane * 4);
                uint2 hdv = *(const uint2*)(Hs + (ew + u) * 256 + 128 + lane * 4);
                float2 s0 = __half22float2(*(__half2*)&hsv.x);
                float2 s1 = __half22float2(*(__half2*)&hsv.y);
                float2 d0 = __half22float2(*(__half2*)&hdv.x);
                float2 d1 = __half22float2(*(__half2*)&hdv.y);
                u64 lo = add2(add2(a_lo[u], pack2(s0.x, s0.y)), pack2(d0.x, d0.y));
                u64 hi = add2(add2(a_hi[u], pack2(s1.x, s1.y)), pack2(d1.x, d1.y));
                float f0, f1, f2, f3;
                unpack2(lo, f0, f1); unpack2(hi, f2, f3);
                __half2 p0 = __floats2half2_rn(f0, f1);
                __half2 p1 = __floats2half2_rn(f2, f3);
                unsigned r0 = *(unsigned*)&p0, r1 = *(unsigned*)&p1;
                asm volatile("st.global.cs.v2.b32 [%0], {%1, %2};"
                             :: "l"(g_mh + (size_t)e * C + 4 * lane), "r"(r0), "r"(r1)
                             : "memory");
                s_lo = add2(s_lo, lo); s_hi = add2(s_hi, hi);
                q_lo = fma2(lo, lo, q_lo); q_hi = fma2(hi, hi, q_hi);
            }
        }

        sts_idx(k & (STAGES - 1), vp);   // indices for tile k+4 into freed slot
        // no second barrier: next iteration's barrier orders these writes
    }

    // -------- block-level BN-stat reduction --------
    __syncthreads();
    for (int i = tid; i < 2 * C; i += blockDim.x) smRed[i] = 0.0f;
    __syncthreads();
    float v0, v1, v2, v3;
    unpack2(s_lo, v0, v1); unpack2(s_hi, v2, v3);
    atomicAdd(&smRed[4 * lane + 0], v0); atomicAdd(&smRed[4 * lane + 1], v1);
    atomicAdd(&smRed[4 * lane + 2], v2); atomicAdd(&smRed[4 * lane + 3], v3);
    unpack2(q_lo, v0, v1); unpack2(q_hi, v2, v3);
    atomicAdd(&smRed[C + 4 * lane + 0], v0); atomicAdd(&smRed[C + 4 * lane + 1], v1);
    atomicAdd(&smRed[C + 4 * lane + 2], v2); atomicAdd(&smRed[C + 4 * lane + 3], v3);
    __syncthreads();
    if (tid < C) {
        atomicAdd(&g_sum[tid],   smRed[tid]);
        atomicAdd(&g_sumsq[tid], smRed[C + tid]);
    }
}

// ================= K3: finalize edge-BN scale/shift =================
__global__ void k_bn_m(const float* __restrict__ gamma, const float* __restrict__ beta, float invE)
{
    int t = threadIdx.x;  // 128 threads
    float mean = g_sum[t] * invE;
    float var  = fmaxf(g_sumsq[t] * invE - mean * mean, 0.0f);
    float s    = gamma[t] * rsqrtf(var + BN_EPS);
    g_bn_s[t] = s;
    g_bn_b[t] = beta[t] - mean * s;
}

// ================= K4: BN + sigmoid*softplus gate + scatter-add =================
// half-warp (16 lanes) per edge; lane-in-half h owns channels [4h, 4h+4). fp16 m.
__global__ void k_edge_pass2(const int* __restrict__ dst, int E)
{
    int lane = threadIdx.x & 31;
    int h    = lane & 15;
    int half = lane >> 4;
    long gw     = (long)blockIdx.x * (blockDim.x >> 5) + (threadIdx.x >> 5);
    long nwarps = (long)gridDim.x * (blockDim.x >> 5);

    float4 sA = *(const float4*)(g_bn_s + 4 * h);
    float4 bA = *(const float4*)(g_bn_b + 4 * h);
    float4 sB = *(const float4*)(g_bn_s + NF + 4 * h);
    float4 bB = *(const float4*)(g_bn_b + NF + 4 * h);

    for (long p = gw; p * 2 < E; p += nwarps) {
        long e = 2 * p + half;
        if (e < E) {
            int d = dst[e];
            const __half* pm = g_mh + (size_t)e * C + 4 * h;
            unsigned v0, v1, v2, v3;
            asm("ld.global.cs.v2.b32 {%0, %1}, [%2];" : "=r"(v0), "=r"(v1) : "l"(pm));
            asm("ld.global.cs.v2.b32 {%0, %1}, [%2];" : "=r"(v2), "=r"(v3) : "l"(pm + NF));
            float2 m1a = __half22float2(*(__half2*)&v0);
            float2 m1b = __half22float2(*(__half2*)&v1);
            float2 m2a = __half22float2(*(__half2*)&v2);
            float2 m2b = __half22float2(*(__half2*)&v3);
            float a0 = fmaf(m1a.x, sA.x, bA.x), a1 = fmaf(m1a.y, sA.y, bA.y);
            float a2 = fmaf(m1b.x, sA.z, bA.z), a3 = fmaf(m1b.y, sA.w, bA.w);
            float g0 = fmaf(m2a.x, sB.x, bB.x), g1 = fmaf(m2a.y, sB.y, bB.y);
            float g2 = fmaf(m2b.x, sB.z, bB.z), g3 = fmaf(m2b.y, sB.w, bB.w);
            float y0 = sigf(a0) * spf(g0);
            float y1 = sigf(a1) * spf(g1);
            float y2 = sigf(a2) * spf(g2);
            float y3 = sigf(a3) * spf(g3);
            float* pd = g_h + (size_t)d * NF + 4 * h;
            asm volatile("red.global.add.v4.f32 [%0], {%1, %2, %3, %4};"
                         :: "l"(pd), "f"(y0), "f"(y1), "f"(y2), "f"(y3) : "memory");
        }
    }
}

// ================= K5: node-BN statistics =================
__global__ void k_node_stats(int N)
{
    __shared__ float smS[NF], smQ[NF];
    int tid = threadIdx.x;
    if (tid < NF) { smS[tid] = 0.0f; smQ[tid] = 0.0f; }
    __syncthreads();
    float s = 0.0f, q = 0.0f;
    long total  = (long)N * NF;
    long stride = (long)gridDim.x * blockDim.x;   // multiple of 64
    for (long i = (long)blockIdx.x * blockDim.x + tid; i < total; i += stride) {
        float v = g_h[i];
        s += v; q += v * v;
    }
    int c = tid & 63;
    atomicAdd(&smS[c], s);
    atomicAdd(&smQ[c], q);
    __syncthreads();
    if (tid < NF) {
        atomicAdd(&g_nsum[tid],   smS[tid]);
        atomicAdd(&g_nsumsq[tid], smQ[tid]);
    }
}

// ================= K6: node BN + residual + softplus =================
__global__ void k_final(const float* __restrict__ nf,
                        const float* __restrict__ gamma, const float* __restrict__ beta,
                        float* __restrict__ out, int N)
{
    __shared__ float sS[NF], sB[NF];
    int tid = threadIdx.x;
    if (tid < NF) {
        float invN = 1.0f / (float)N;
        float mean = g_nsum[tid] * invN;
        float var  = fmaxf(g_nsumsq[tid] * invN - mean * mean, 0.0f);
        float s    = gamma[tid] * rsqrtf(var + BN_EPS);
        sS[tid] = s;
        sB[tid] = beta[tid] - mean * s;
    }
    __syncthreads();
    long total  = (long)N * NF;
    long stride = (long)gridDim.x * blockDim.x;   // multiple of 64
    int  c = tid & 63;
    float s = sS[c], b = sB[c];
    for (long i = (long)blockIdx.x * blockDim.x + tid; i < total; i += stride) {
        float x = nf[i] + fmaf(g_h[i], s, b);
        out[i]  = fmaxf(x, 0.0f) + __logf(1.0f + __expf(-fabsf(x)));
    }
}

// ================= launch =================
extern "C" void kernel_launch(void* const* d_in, const int* in_sizes, int n_in,
                              void* d_out, int out_size)
{
    const float* node_feats = (const float*)d_in[0];
    const float* edge_feats = (const float*)d_in[1];
    const float* W_src   = (const float*)d_in[2];
    const float* b_src   = (const float*)d_in[3];
    const float* W_dst   = (const float*)d_in[4];
    const float* b_dst   = (const float*)d_in[5];
    const float* W_edge  = (const float*)d_in[6];
    const float* b_edge  = (const float*)d_in[7];
    const float* gamma_m = (const float*)d_in[8];
    const float* beta_m  = (const float*)d_in[9];
    const float* gamma_n = (const float*)d_in[10];
    const float* beta_n  = (const float*)d_in[11];
    const int*   src     = (const int*)d_in[12];
    const int*   dst     = (const int*)d_in[13];

    int N = in_sizes[0] / NF;
    int E = in_sizes[12];

    void *ph, *psum, *psumsq, *pnsum, *pnsumsq;
    cudaGetSymbolAddress(&ph, g_h);
    cudaGetSymbolAddress(&psum, g_sum);
    cudaGetSymbolAddress(&psumsq, g_sumsq);
    cudaGetSymbolAddress(&pnsum, g_nsum);
    cudaGetSymbolAddress(&pnsumsq, g_nsumsq);
    cudaMemsetAsync(ph, 0, (size_t)N * NF * sizeof(float));
    cudaMemsetAsync(psum, 0, C * sizeof(float));
    cudaMemsetAsync(psumsq, 0, C * sizeof(float));
    cudaMemsetAsync(pnsum, 0, NF * sizeof(float));
    cudaMemsetAsync(pnsumsq, 0, NF * sizeof(float));

    int smem1 = (2 * NF * C + 32 * NF) * (int)sizeof(float);   // 72 KB
    cudaFuncSetAttribute(k_node_proj, cudaFuncAttributeMaxDynamicSharedMemorySize, smem1);

    // K2 dynamic smem: W 16KB + X 4x4KB + H 4x16KB = 96KB -> 2 blocks/SM
    int smem2 = 16384 + STAGES * TILE_E * EF * 4 + STAGES * TILE_E * 256 * 2;
    cudaFuncSetAttribute(k_edge_pass1, cudaFuncAttributeMaxDynamicSharedMemorySize, smem2);

    k_node_proj<<<1184, 256, smem1>>>(node_feats, W_src, b_src, W_dst, b_dst, N);
    k_edge_pass1<<<296, 256, smem2>>>(edge_feats, W_edge, b_edge, src, dst, E);
    k_bn_m<<<1, 128>>>(gamma_m, beta_m, 1.0f / (float)E);
    k_edge_pass2<<<2368, 256>>>(dst, E);
    k_node_stats<<<512, 256>>>(N);
    k_final<<<512, 256>>>(node_feats, gamma_n, beta_n, (float*)d_out, N);
}